// round 7
// baseline (speedup 1.0000x reference)
#include <cuda_runtime.h>
#include <math.h>
#include <stdint.h>

// Problem constants
#define B_SZ    512
#define DFEAT   2048
#define DATTR   312
#define DATTR_P 320              // N padded (partial rows only)

// GEMM tiling: fp32x2 packed-FFMA SIMT GEMM
#define BM      128              // M per CTA (16 thr * 8 rows)
#define BN      32               // N per CTA (8 thr * 4 cols)
#define BK      16               // K per smem tile
#define SPLITK  8
#define KSLICE  (DFEAT / SPLITK) // 256
#define SA_STR  130              // sA row stride (words): conflict-free fill+load
#define SB_STR  66               // sB row stride (words): 64 dup + 2 pad

// Scratch (__device__ globals: allocation-free)
__device__ float g_partial[SPLITK][B_SZ][DATTR_P];
__device__ float g_Sf[B_SZ];
__device__ unsigned int g_done;   // last-block counter (reset each call)

// ---------------------------------------------------------------------------
// Kernel 1: D = X @ W via packed fp32x2 FMA (fma.rn.f32x2, 2 FMA/instr).
// grid (10 n-tiles, 4 m-tiles, 8 k-slices) = 320 CTAs, 128 threads.
// Thread tile: 4 m-pairs (8 rows) x 4 cols. A transposed in smem (m-pairs are
// natural 64-bit loads); B duplicated in smem ({v,v} pairs are natural 64-bit
// loads). No W transpose kernel, no bf16 conversion.
// ---------------------------------------------------------------------------
__global__ __launch_bounds__(128) void gemm_f32x2_kernel(
    const float* __restrict__ X,    // [512, 2048]
    const float* __restrict__ Wm)   // [2048, 312]
{
    __shared__ __align__(16) float sA[BK][SA_STR];   // sA[k][m]
    __shared__ __align__(16) float sB[BK][SB_STR];   // sB[k][2n] duplicated

    const int tid = threadIdx.x;
    const int tn  = tid & 7;     // 0..7  -> 4 cols each
    const int tm  = tid >> 3;    // 0..15 -> 8 rows (4 pairs) each
    const int nt = blockIdx.x, mt = blockIdx.y, zs = blockIdx.z;

    const int mBase = mt * BM;
    const int nBase = nt * BN;
    const int k0    = zs * KSLICE;

    // fill-role indices
    const int fa_k4 = tid & 3;          // float4 chunk over k (k = fa_k4*4 + j)
    const int fa_m  = tid >> 2;         // 0..31 (x4 iterations -> 128 rows)
    const int fb_k  = tid >> 3;         // 0..15
    const int fb_col = nBase + (tid & 7) * 4;
    const bool b_ok  = (fb_col < DATTR);

    unsigned long long acc[16];
    #pragma unroll
    for (int i = 0; i < 16; i++) acc[i] = 0ULL;

    float4 xa[4], wb;

    // prefetch tile 0
    #pragma unroll
    for (int it = 0; it < 4; it++)
        xa[it] = *(const float4*)(X + (size_t)(mBase + fa_m + 32 * it) * DFEAT + k0 + fa_k4 * 4);
    wb = b_ok ? *(const float4*)(Wm + (size_t)(k0 + fb_k) * DATTR + fb_col)
              : make_float4(0.f, 0.f, 0.f, 0.f);

    for (int kt = 0; kt < KSLICE; kt += BK) {
        // store prefetched tile
        #pragma unroll
        for (int it = 0; it < 4; it++) {
            const int m = fa_m + 32 * it;
            sA[fa_k4 * 4 + 0][m] = xa[it].x;
            sA[fa_k4 * 4 + 1][m] = xa[it].y;
            sA[fa_k4 * 4 + 2][m] = xa[it].z;
            sA[fa_k4 * 4 + 3][m] = xa[it].w;
        }
        {
            float2* row = (float2*)&sB[fb_k][0];
            const int n0 = (tid & 7) * 4;
            row[n0 + 0] = make_float2(wb.x, wb.x);
            row[n0 + 1] = make_float2(wb.y, wb.y);
            row[n0 + 2] = make_float2(wb.z, wb.z);
            row[n0 + 3] = make_float2(wb.w, wb.w);
        }
        __syncthreads();

        // prefetch next tile while computing
        if (kt + BK < KSLICE) {
            const int k = k0 + kt + BK;
            #pragma unroll
            for (int it = 0; it < 4; it++)
                xa[it] = *(const float4*)(X + (size_t)(mBase + fa_m + 32 * it) * DFEAT + k + fa_k4 * 4);
            wb = b_ok ? *(const float4*)(Wm + (size_t)(k + fb_k) * DATTR + fb_col)
                      : make_float4(0.f, 0.f, 0.f, 0.f);
        }

        #pragma unroll
        for (int k = 0; k < BK; k++) {
            unsigned long long a[4], b[4];
            #pragma unroll
            for (int p = 0; p < 4; p++)
                a[p] = *(const unsigned long long*)&sA[k][tm * 8 + 2 * p];
            #pragma unroll
            for (int q = 0; q < 4; q++)
                b[q] = *(const unsigned long long*)&sB[k][(tn * 4 + q) * 2];
            #pragma unroll
            for (int p = 0; p < 4; p++) {
                #pragma unroll
                for (int q = 0; q < 4; q++) {
                    asm volatile("fma.rn.f32x2 %0, %1, %2, %0;"
                                 : "+l"(acc[p * 4 + q])
                                 : "l"(a[p]), "l"(b[q]));
                }
            }
        }
        __syncthreads();
    }

    // Epilogue: unpack pairs, write fp32 partials
    #pragma unroll
    for (int p = 0; p < 4; p++) {
        const int r0 = mBase + tm * 8 + 2 * p;
        #pragma unroll
        for (int q = 0; q < 4; q++) {
            const unsigned long long u = acc[p * 4 + q];
            const int col = nBase + tn * 4 + q;
            g_partial[zs][r0    ][col] = __uint_as_float((unsigned)(u & 0xffffffffu));
            g_partial[zs][r0 + 1][col] = __uint_as_float((unsigned)(u >> 32));
        }
    }
}

// ---------------------------------------------------------------------------
// Kernel 2 (fused): per-row S[i] = rowsum - DATTR*LSE, then last block
// computes the pair loss.  grid 512, block 128.
// ---------------------------------------------------------------------------
__global__ __launch_bounds__(128) void rowstats_pair_kernel(
    const float* __restrict__ bvec, const int* __restrict__ labw,
    float* __restrict__ out)
{
    const int i   = blockIdx.x;
    const int tid = threadIdx.x;

    __shared__ float vals[DATTR_P];
    __shared__ float sred[4];

    // float4 partial reduction: 80 float4 cols, 8 slices each (MLP=8)
    if (tid < 80) {
        float4 a = (tid < 78) ? *(const float4*)(bvec + tid * 4)
                              : make_float4(0.f, 0.f, 0.f, 0.f);
        #pragma unroll
        for (int s = 0; s < SPLITK; s++) {
            const float4 p = *(const float4*)&g_partial[s][i][tid * 4];
            a.x += p.x; a.y += p.y; a.z += p.z; a.w += p.w;
        }
        *(float4*)&vals[tid * 4] = a;
    }
    __syncthreads();

    // row max over first 312 cols
    float m = -1e30f;
    for (int c = tid; c < DATTR; c += 128) m = fmaxf(m, vals[c]);
    #pragma unroll
    for (int o = 16; o; o >>= 1) m = fmaxf(m, __shfl_xor_sync(0xffffffffu, m, o));
    if ((tid & 31) == 0) sred[tid >> 5] = m;
    __syncthreads();
    m = fmaxf(fmaxf(sred[0], sred[1]), fmaxf(sred[2], sred[3]));

    __shared__ float sse[4], srs[4];
    float se = 0.f, rs = 0.f;
    for (int c = tid; c < DATTR; c += 128) {
        const float v = vals[c];
        se += expf(v - m);
        rs += v;
    }
    #pragma unroll
    for (int o = 16; o; o >>= 1) {
        se += __shfl_xor_sync(0xffffffffu, se, o);
        rs += __shfl_xor_sync(0xffffffffu, rs, o);
    }
    if ((tid & 31) == 0) { sse[tid >> 5] = se; srs[tid >> 5] = rs; }
    __syncthreads();

    if (tid == 0) {
        const float seT = sse[0] + sse[1] + sse[2] + sse[3];
        const float rsT = srs[0] + srs[1] + srs[2] + srs[3];
        g_Sf[i] = rsT - (float)DATTR * (m + logf(seT));
    }

    // ---- last-block pair loss ----
    __shared__ int s_last;
    __threadfence();
    if (tid == 0) {
        const unsigned int old = atomicAdd(&g_done, 1u);
        s_last = (old == (unsigned int)(gridDim.x - 1));
    }
    __syncthreads();
    if (!s_last) return;

    __shared__ int   slab[B_SZ];
    __shared__ float sS[B_SZ];
    __shared__ int   s_not64;
    __shared__ float swsum[4];
    __shared__ unsigned int swcnt[4];

    if (tid == 0) s_not64 = 0;
    __syncthreads();
    // label dtype sniff: int64 buffers have zero odd words (labels < 150)
    for (int t = tid; t < 256; t += 128)
        if (labw[2 * t + 1] != 0) atomicOr(&s_not64, 1);
    __syncthreads();
    const bool is64 = (s_not64 == 0);
    for (int t = tid; t < B_SZ; t += 128) {
        slab[t] = is64 ? labw[2 * t] : labw[t];
        sS[t]   = __ldcg(&g_Sf[t]);
    }
    __syncthreads();

    float        local = 0.f;
    unsigned int cnt   = 0;
    for (int ii = tid; ii < B_SZ; ii += 128) {
        const int   li = slab[ii];
        const float Si = sS[ii];
        for (int j = ii + 1; j < B_SZ; j++)
            if (slab[j] == li) { local += sS[j] - Si; cnt++; }
    }
    #pragma unroll
    for (int o = 16; o; o >>= 1) {
        local += __shfl_xor_sync(0xffffffffu, local, o);
        cnt   += __shfl_xor_sync(0xffffffffu, cnt, o);
    }
    if ((tid & 31) == 0) { swsum[tid >> 5] = local; swcnt[tid >> 5] = cnt; }
    __syncthreads();

    if (tid == 0) {
        const float        s = swsum[0] + swsum[1] + swsum[2] + swsum[3];
        const unsigned int c = swcnt[0] + swcnt[1] + swcnt[2] + swcnt[3];
        out[0] = (c > 0) ? (s / (float)c) : s;
        g_done = 0;   // reset for next graph replay (deterministic)
    }
}

// ---------------------------------------------------------------------------
extern "C" void kernel_launch(void* const* d_in, const int* in_sizes, int n_in,
                              void* d_out, int out_size)
{
    const float* x   = (const float*)d_in[0];      // [512, 2048]
    const float* Wm  = (const float*)d_in[1];      // [2048, 312]
    const float* b   = (const float*)d_in[2];      // [312]
    // d_in[3] = seen_att : unused (cancels exactly for same-label pairs)
    const int*   lab = (const int*)d_in[4];        // [512] labels

    gemm_f32x2_kernel<<<dim3(DATTR_P / BN, B_SZ / BM, SPLITK), 128>>>(x, Wm);
    rowstats_pair_kernel<<<B_SZ, 128>>>(b, lab, (float*)d_out);
}

// round 8
// speedup vs baseline: 1.8105x; 1.8105x over previous
#include <cuda_runtime.h>
#include <cuda_bf16.h>
#include <math.h>
#include <stdint.h>

// Problem constants
#define B_SZ    512
#define DFEAT   2048
#define DATTR   312
#define DATTR_P 320              // N padded to 5*64

// GEMM tiling: D[512,320] = X[512,2048] @ W^T, bf16 hi/lo x4-term split
#define MT_BLK  128              // M per CTA
#define NT_BLK  64               // N per CTA
#define BKT     32               // K per smem tile
#define KSPLIT  8
#define KSLICE  (DFEAT / KSPLIT) // 256

// Scratch (__device__ globals: allocation-free, zero-initialized at load)
__device__ __nv_bfloat16 g_WhiT[DATTR_P * DFEAT];   // W^T K-major; rows >=312 stay 0
__device__ __nv_bfloat16 g_WloT[DATTR_P * DFEAT];
__device__ float g_partial[KSPLIT][B_SZ][DATTR_P];
__device__ float g_Sf[B_SZ];

// ---------------------------------------------------------------------------
// Kernel 0: W [2048,312] -> W^T [320,2048] bf16 hi/lo, fully vectorized.
// Tile 64k x 32n. Loads: float4 coalesced. Writes: uint4 (8 bf16) along k.
// grid (10 n-tiles, 32 k-tiles) = 320 blocks, 256 threads.
// ---------------------------------------------------------------------------
__global__ __launch_bounds__(256) void split_w_kernel(const float* __restrict__ Wm)
{
    __shared__ float t[64][33];
    const int n0 = blockIdx.x * 32, k0 = blockIdx.y * 64;
    const int tid = threadIdx.x;

    // Load 64 rows x 32 floats = 512 float4; 2 per thread.
    {
        const int r = tid >> 2, q = tid & 3;
        #pragma unroll
        for (int h = 0; h < 2; h++) {
            const int qq = q + 4 * h;                  // 0..7 -> n_local = qq*4
            const int n = n0 + (qq & 7) * 4;
            // 312 % 4 == 0: each float4 is fully valid or fully out of range
            const float4 v = (n < DATTR)
                ? *(const float4*)(Wm + (size_t)(k0 + r) * DATTR + n)
                : make_float4(0.f, 0.f, 0.f, 0.f);
            // only qq in 0..7 covering n_local 0..31; h selects upper half
            t[r][qq * 4 + 0] = v.x;
            t[r][qq * 4 + 1] = v.y;
            t[r][qq * 4 + 2] = v.z;
            t[r][qq * 4 + 3] = v.w;
        }
    }
    __syncthreads();

    // Write: thread -> (n_local = tid>>3, k-chunk = tid&7), 8 bf16 per array.
    {
        const int nl = tid >> 3, kc = tid & 7;
        const int n = n0 + nl;
        if (n < DATTR) {
            __nv_bfloat16 hi[8], lo[8];
            #pragma unroll
            for (int j = 0; j < 8; j++) {
                const float v = t[kc * 8 + j][nl];
                hi[j] = __float2bfloat16_rn(v);
                lo[j] = __float2bfloat16_rn(v - __bfloat162float(hi[j]));
            }
            const size_t off = (size_t)n * DFEAT + k0 + kc * 8;
            *(uint4*)(g_WhiT + off) = *(const uint4*)hi;
            *(uint4*)(g_WloT + off) = *(const uint4*)lo;
        }
    }
}

// ---------------------------------------------------------------------------
// Kernel 1: fused bf16 mma.sync GEMM with inline X hi/lo split (round-6,
// measured ~14us). grid (5,4,8) = 160 CTAs, 256 threads (8 warps).
// ---------------------------------------------------------------------------
__global__ __launch_bounds__(256) void mma_gemm_kernel(const float* __restrict__ X)
{
    __shared__ __nv_bfloat16 sAhi[MT_BLK][40];
    __shared__ __nv_bfloat16 sAlo[MT_BLK][40];
    __shared__ __nv_bfloat16 sBhi[NT_BLK][40];
    __shared__ __nv_bfloat16 sBlo[NT_BLK][40];

    const int tid   = threadIdx.x;
    const int wid   = tid >> 5;
    const int lane  = tid & 31;
    const int warpM = wid >> 1;
    const int warpN = wid & 1;
    const int nt = blockIdx.x, mt = blockIdx.y, zs = blockIdx.z;

    const int mBase = mt * MT_BLK;
    const int nBase = nt * NT_BLK;
    const int k0    = zs * KSLICE;

    const int lq = lane >> 2;
    const int lr = lane & 3;

    float4 xa[4];
    uint4  wh, wl;
    const int arow = tid >> 3, ac = tid & 7;
    const int wrow = tid >> 2, wc = tid & 3;

    float acc[2][4][4] = {};

    {
        const int k = k0;
        #pragma unroll
        for (int it = 0; it < 4; it++)
            xa[it] = *(const float4*)(X + (size_t)(mBase + arow + 32 * it) * DFEAT + k + ac * 4);
        wh = *(const uint4*)(g_WhiT + (size_t)(nBase + wrow) * DFEAT + k + wc * 8);
        wl = *(const uint4*)(g_WloT + (size_t)(nBase + wrow) * DFEAT + k + wc * 8);
    }

    for (int kt = 0; kt < KSLICE; kt += BKT) {
        #pragma unroll
        for (int it = 0; it < 4; it++) {
            const float4 v = xa[it];
            const int row = arow + 32 * it;
            const __nv_bfloat16 h0 = __float2bfloat16_rn(v.x), h1 = __float2bfloat16_rn(v.y);
            const __nv_bfloat16 h2 = __float2bfloat16_rn(v.z), h3 = __float2bfloat16_rn(v.w);
            *(__nv_bfloat162*)&sAhi[row][ac * 4]     = __nv_bfloat162(h0, h1);
            *(__nv_bfloat162*)&sAhi[row][ac * 4 + 2] = __nv_bfloat162(h2, h3);
            *(__nv_bfloat162*)&sAlo[row][ac * 4] = __nv_bfloat162(
                __float2bfloat16_rn(v.x - __bfloat162float(h0)),
                __float2bfloat16_rn(v.y - __bfloat162float(h1)));
            *(__nv_bfloat162*)&sAlo[row][ac * 4 + 2] = __nv_bfloat162(
                __float2bfloat16_rn(v.z - __bfloat162float(h2)),
                __float2bfloat16_rn(v.w - __bfloat162float(h3)));
        }
        *(uint4*)&sBhi[wrow][wc * 8] = wh;
        *(uint4*)&sBlo[wrow][wc * 8] = wl;
        __syncthreads();

        if (kt + BKT < KSLICE) {
            const int k = k0 + kt + BKT;
            #pragma unroll
            for (int it = 0; it < 4; it++)
                xa[it] = *(const float4*)(X + (size_t)(mBase + arow + 32 * it) * DFEAT + k + ac * 4);
            wh = *(const uint4*)(g_WhiT + (size_t)(nBase + wrow) * DFEAT + k + wc * 8);
            wl = *(const uint4*)(g_WloT + (size_t)(nBase + wrow) * DFEAT + k + wc * 8);
        }

        #pragma unroll
        for (int kk = 0; kk < BKT; kk += 16) {
            uint32_t ahi[2][4], alo[2][4];
            #pragma unroll
            for (int am = 0; am < 2; am++) {
                const int r = warpM * 32 + am * 16 + lq;
                ahi[am][0] = *(const uint32_t*)&sAhi[r    ][kk + lr * 2    ];
                ahi[am][1] = *(const uint32_t*)&sAhi[r + 8][kk + lr * 2    ];
                ahi[am][2] = *(const uint32_t*)&sAhi[r    ][kk + lr * 2 + 8];
                ahi[am][3] = *(const uint32_t*)&sAhi[r + 8][kk + lr * 2 + 8];
                alo[am][0] = *(const uint32_t*)&sAlo[r    ][kk + lr * 2    ];
                alo[am][1] = *(const uint32_t*)&sAlo[r + 8][kk + lr * 2    ];
                alo[am][2] = *(const uint32_t*)&sAlo[r    ][kk + lr * 2 + 8];
                alo[am][3] = *(const uint32_t*)&sAlo[r + 8][kk + lr * 2 + 8];
            }
            uint32_t bhi[4][2], blo[4][2];
            #pragma unroll
            for (int bn = 0; bn < 4; bn++) {
                const int n = warpN * 32 + bn * 8 + lq;
                bhi[bn][0] = *(const uint32_t*)&sBhi[n][kk + lr * 2    ];
                bhi[bn][1] = *(const uint32_t*)&sBhi[n][kk + lr * 2 + 8];
                blo[bn][0] = *(const uint32_t*)&sBlo[n][kk + lr * 2    ];
                blo[bn][1] = *(const uint32_t*)&sBlo[n][kk + lr * 2 + 8];
            }
            #pragma unroll
            for (int am = 0; am < 2; am++) {
                #pragma unroll
                for (int bn = 0; bn < 4; bn++) {
                    float* c = acc[am][bn];
                    #define MMA(AV, BV)                                               \
                        asm volatile(                                                  \
                            "mma.sync.aligned.m16n8k16.row.col.f32.bf16.bf16.f32 "    \
                            "{%0,%1,%2,%3}, {%4,%5,%6,%7}, {%8,%9}, {%0,%1,%2,%3};"   \
                            : "+f"(c[0]), "+f"(c[1]), "+f"(c[2]), "+f"(c[3])           \
                            : "r"(AV[0]), "r"(AV[1]), "r"(AV[2]), "r"(AV[3]),          \
                              "r"(BV[0]), "r"(BV[1]))
                    MMA(ahi[am], bhi[bn]);
                    MMA(ahi[am], blo[bn]);
                    MMA(alo[am], bhi[bn]);
                    MMA(alo[am], blo[bn]);
                    #undef MMA
                }
            }
        }
        __syncthreads();
    }

    #pragma unroll
    for (int am = 0; am < 2; am++) {
        const int row0 = mBase + warpM * 32 + am * 16 + lq;
        #pragma unroll
        for (int bn = 0; bn < 4; bn++) {
            const int col = nBase + warpN * 32 + bn * 8 + lr * 2;
            *(float2*)&g_partial[zs][row0    ][col] = make_float2(acc[am][bn][0], acc[am][bn][1]);
            *(float2*)&g_partial[zs][row0 + 8][col] = make_float2(acc[am][bn][2], acc[am][bn][3]);
        }
    }
}

// ---------------------------------------------------------------------------
// Kernel 2: per-row S[i] = rowsum(pre_i) - DATTR * logsumexp(pre_i).
// grid 512, block 256: slice reduction split across 160 threads (2x80).
// ---------------------------------------------------------------------------
__global__ __launch_bounds__(256) void rowstats_kernel(const float* __restrict__ bvec)
{
    const int i   = blockIdx.x;
    const int tid = threadIdx.x;

    __shared__ float vhalf[2][DATTR_P];
    __shared__ float vals[DATTR_P];
    __shared__ float sred[8], sse[8], srs[8];

    if (tid < 160) {
        const int half = (tid < 80) ? 0 : 1;
        const int c4   = (tid < 80) ? tid : (tid - 80);
        float4 a = make_float4(0.f, 0.f, 0.f, 0.f);
        #pragma unroll
        for (int s = 0; s < 4; s++) {
            const float4 p = *(const float4*)&g_partial[half * 4 + s][i][c4 * 4];
            a.x += p.x; a.y += p.y; a.z += p.z; a.w += p.w;
        }
        *(float4*)&vhalf[half][c4 * 4] = a;
    }
    __syncthreads();
    if (tid < 80) {
        float4 a = *(const float4*)&vhalf[0][tid * 4];
        const float4 c = *(const float4*)&vhalf[1][tid * 4];
        const float4 bb = (tid < 78) ? *(const float4*)(bvec + tid * 4)
                                     : make_float4(0.f, 0.f, 0.f, 0.f);
        a.x += c.x + bb.x; a.y += c.y + bb.y;
        a.z += c.z + bb.z; a.w += c.w + bb.w;
        *(float4*)&vals[tid * 4] = a;
    }
    __syncthreads();

    float m = -1e30f;
    for (int c = tid; c < DATTR; c += 256) m = fmaxf(m, vals[c]);
    #pragma unroll
    for (int o = 16; o; o >>= 1) m = fmaxf(m, __shfl_xor_sync(0xffffffffu, m, o));
    if ((tid & 31) == 0) sred[tid >> 5] = m;
    __syncthreads();
    m = sred[0];
    #pragma unroll
    for (int w = 1; w < 8; w++) m = fmaxf(m, sred[w]);

    float se = 0.f, rs = 0.f;
    for (int c = tid; c < DATTR; c += 256) {
        const float v = vals[c];
        se += expf(v - m);
        rs += v;
    }
    #pragma unroll
    for (int o = 16; o; o >>= 1) {
        se += __shfl_xor_sync(0xffffffffu, se, o);
        rs += __shfl_xor_sync(0xffffffffu, rs, o);
    }
    if ((tid & 31) == 0) { sse[tid >> 5] = se; srs[tid >> 5] = rs; }
    __syncthreads();

    if (tid == 0) {
        float seT = 0.f, rsT = 0.f;
        #pragma unroll
        for (int w = 0; w < 8; w++) { seT += sse[w]; rsT += srs[w]; }
        g_Sf[i] = rsT - (float)DATTR * (m + logf(seT));
    }
}

// ---------------------------------------------------------------------------
// Kernel 3: loss = mean over same-label upper pairs of (S_j - S_i).
// Single block, 512 threads (thread t owns row i = t).
// Label dtype sniff: int64 buffers have zero odd words (labels < 150).
// ---------------------------------------------------------------------------
__global__ __launch_bounds__(512) void pair_loss_kernel(
    const int* __restrict__ labw, float* __restrict__ out)
{
    __shared__ int           slab[B_SZ];
    __shared__ int           s_not64;
    __shared__ float         sS[B_SZ];
    __shared__ float         swsum[16];
    __shared__ unsigned int  swcnt[16];

    const int t = threadIdx.x;
    if (t == 0) s_not64 = 0;
    __syncthreads();

    if (t < 256 && labw[2 * t + 1] != 0) atomicOr(&s_not64, 1);
    __syncthreads();

    const bool is64 = (s_not64 == 0);
    slab[t] = is64 ? labw[2 * t] : labw[t];
    sS[t]   = g_Sf[t];
    __syncthreads();

    const int   li = slab[t];
    const float Si = sS[t];
    float        local = 0.f;
    unsigned int cnt   = 0;

    for (int j = t + 1; j < B_SZ; j++) {
        if (slab[j] == li) { local += sS[j] - Si; cnt++; }
    }

    #pragma unroll
    for (int o = 16; o; o >>= 1) {
        local += __shfl_xor_sync(0xffffffffu, local, o);
        cnt   += __shfl_xor_sync(0xffffffffu, cnt, o);
    }
    if ((t & 31) == 0) { swsum[t >> 5] = local; swcnt[t >> 5] = cnt; }
    __syncthreads();

    if (t == 0) {
        float s = 0.f; unsigned int c = 0;
        #pragma unroll
        for (int w = 0; w < 16; w++) { s += swsum[w]; c += swcnt[w]; }
        out[0] = (c > 0) ? (s / (float)c) : s;
    }
}

// ---------------------------------------------------------------------------
extern "C" void kernel_launch(void* const* d_in, const int* in_sizes, int n_in,
                              void* d_out, int out_size)
{
    const float* x   = (const float*)d_in[0];      // [512, 2048]
    const float* Wm  = (const float*)d_in[1];      // [2048, 312]
    const float* b   = (const float*)d_in[2];      // [312]
    // d_in[3] = seen_att : unused (cancels exactly for same-label pairs)
    const int*   lab = (const int*)d_in[4];        // [512] labels

    split_w_kernel<<<dim3(10, 32), 256>>>(Wm);
    mma_gemm_kernel<<<dim3(5, 4, KSPLIT), 256>>>(x);
    rowstats_kernel<<<B_SZ, 256>>>(b);
    pair_loss_kernel<<<1, B_SZ>>>(lab, (float*)d_out);
}

// round 10
// speedup vs baseline: 2.0503x; 1.1324x over previous
#include <cuda_runtime.h>
#include <cuda_bf16.h>
#include <math.h>
#include <stdint.h>

// Problem constants
#define B_SZ    512
#define DFEAT   2048
#define DATTR   312
#define DATTR_P 320              // N padded to 4*80

// GEMM tiling: D[512,320] = X[512,2048] @ W^T, bf16 hi/lo x4-term split
#define MT_BLK  128              // M per CTA
#define NT_BLK  80               // N per CTA -> 4 n-tiles, grid 128 = one wave
#define BKT     32               // K per smem tile
#define KSPLIT  8
#define KSLICE  (DFEAT / KSPLIT) // 256

// Scratch (__device__ globals: allocation-free, zero-initialized at load)
__device__ __nv_bfloat16 g_WhiT[DATTR_P * DFEAT];   // W^T K-major; rows >=312 stay 0
__device__ __nv_bfloat16 g_WloT[DATTR_P * DFEAT];
__device__ float g_partial[KSPLIT][B_SZ][DATTR_P];
__device__ float g_Sf[B_SZ];

// ---------------------------------------------------------------------------
// Kernel 0: W [2048,312] -> W^T [320,2048] bf16 hi/lo, vectorized.
// grid (10 n-tiles of 32, 32 k-tiles of 64) = 320 blocks, 256 threads.
// ---------------------------------------------------------------------------
__global__ __launch_bounds__(256) void split_w_kernel(const float* __restrict__ Wm)
{
    __shared__ float t[64][33];
    const int n0 = blockIdx.x * 32, k0 = blockIdx.y * 64;
    const int tid = threadIdx.x;

    {
        const int r = tid >> 2, q = tid & 3;
        #pragma unroll
        for (int h = 0; h < 2; h++) {
            const int qq = q + 4 * h;
            const int n = n0 + qq * 4;
            const float4 v = (n < DATTR)
                ? *(const float4*)(Wm + (size_t)(k0 + r) * DATTR + n)
                : make_float4(0.f, 0.f, 0.f, 0.f);
            t[r][qq * 4 + 0] = v.x;
            t[r][qq * 4 + 1] = v.y;
            t[r][qq * 4 + 2] = v.z;
            t[r][qq * 4 + 3] = v.w;
        }
    }
    __syncthreads();

    {
        const int nl = tid >> 3, kc = tid & 7;
        const int n = n0 + nl;
        if (n < DATTR) {
            __nv_bfloat16 hi[8], lo[8];
            #pragma unroll
            for (int j = 0; j < 8; j++) {
                const float v = t[kc * 8 + j][nl];
                hi[j] = __float2bfloat16_rn(v);
                lo[j] = __float2bfloat16_rn(v - __bfloat162float(hi[j]));
            }
            const size_t off = (size_t)n * DFEAT + k0 + kc * 8;
            *(uint4*)(g_WhiT + off) = *(const uint4*)hi;
            *(uint4*)(g_WloT + off) = *(const uint4*)lo;
        }
    }
}

// ---------------------------------------------------------------------------
// Kernel 1: fused bf16 mma.sync GEMM with inline X hi/lo split.
// grid (4 n-tiles, 4 m-tiles, 8 k-slices) = 128 CTAs (one wave), 256 threads.
// Warp grid 4(m) x 2(n); warp tile 32x40 = 2x5 atoms; 4 mma chains (hi/lo^2).
// ---------------------------------------------------------------------------
__global__ __launch_bounds__(256) void mma_gemm_kernel(const float* __restrict__ X)
{
    __shared__ __nv_bfloat16 sAhi[MT_BLK][40];
    __shared__ __nv_bfloat16 sAlo[MT_BLK][40];
    __shared__ __nv_bfloat16 sBhi[NT_BLK][40];
    __shared__ __nv_bfloat16 sBlo[NT_BLK][40];

    const int tid   = threadIdx.x;
    const int wid   = tid >> 5;
    const int lane  = tid & 31;
    const int warpM = wid >> 1;          // 0..3
    const int warpN = wid & 1;           // 0..1
    const int nt = blockIdx.x, mt = blockIdx.y, zs = blockIdx.z;

    const int mBase = mt * MT_BLK;
    const int nBase = nt * NT_BLK;
    const int k0    = zs * KSLICE;

    const int lq = lane >> 2;
    const int lr = lane & 3;

    // fill/prefetch roles
    float4 xa[4];
    uint4  wh0, wl0, wh1, wl1;
    const int arow  = tid >> 3, ac = tid & 7;        // A: 1024 float4, 4/thread
    const int wrow0 = tid >> 2, wc0 = tid & 3;       // B: 320 uint4: idx=tid
    const int wrow1 = 64 + (tid >> 2);               //    and idx=256+tid (tid<64)
    const bool bsec = (tid < 64);

    float acc[2][5][4] = {};

    {
        const int k = k0;
        #pragma unroll
        for (int it = 0; it < 4; it++)
            xa[it] = *(const float4*)(X + (size_t)(mBase + arow + 32 * it) * DFEAT + k + ac * 4);
        wh0 = *(const uint4*)(g_WhiT + (size_t)(nBase + wrow0) * DFEAT + k + wc0 * 8);
        wl0 = *(const uint4*)(g_WloT + (size_t)(nBase + wrow0) * DFEAT + k + wc0 * 8);
        if (bsec) {
            wh1 = *(const uint4*)(g_WhiT + (size_t)(nBase + wrow1) * DFEAT + k + wc0 * 8);
            wl1 = *(const uint4*)(g_WloT + (size_t)(nBase + wrow1) * DFEAT + k + wc0 * 8);
        }
    }

    for (int kt = 0; kt < KSLICE; kt += BKT) {
        #pragma unroll
        for (int it = 0; it < 4; it++) {
            const float4 v = xa[it];
            const int row = arow + 32 * it;
            const __nv_bfloat16 h0 = __float2bfloat16_rn(v.x), h1 = __float2bfloat16_rn(v.y);
            const __nv_bfloat16 h2 = __float2bfloat16_rn(v.z), h3 = __float2bfloat16_rn(v.w);
            *(__nv_bfloat162*)&sAhi[row][ac * 4]     = __nv_bfloat162(h0, h1);
            *(__nv_bfloat162*)&sAhi[row][ac * 4 + 2] = __nv_bfloat162(h2, h3);
            *(__nv_bfloat162*)&sAlo[row][ac * 4] = __nv_bfloat162(
                __float2bfloat16_rn(v.x - __bfloat162float(h0)),
                __float2bfloat16_rn(v.y - __bfloat162float(h1)));
            *(__nv_bfloat162*)&sAlo[row][ac * 4 + 2] = __nv_bfloat162(
                __float2bfloat16_rn(v.z - __bfloat162float(h2)),
                __float2bfloat16_rn(v.w - __bfloat162float(h3)));
        }
        *(uint4*)&sBhi[wrow0][wc0 * 8] = wh0;
        *(uint4*)&sBlo[wrow0][wc0 * 8] = wl0;
        if (bsec) {
            *(uint4*)&sBhi[wrow1][wc0 * 8] = wh1;
            *(uint4*)&sBlo[wrow1][wc0 * 8] = wl1;
        }
        __syncthreads();

        if (kt + BKT < KSLICE) {
            const int k = k0 + kt + BKT;
            #pragma unroll
            for (int it = 0; it < 4; it++)
                xa[it] = *(const float4*)(X + (size_t)(mBase + arow + 32 * it) * DFEAT + k + ac * 4);
            wh0 = *(const uint4*)(g_WhiT + (size_t)(nBase + wrow0) * DFEAT + k + wc0 * 8);
            wl0 = *(const uint4*)(g_WloT + (size_t)(nBase + wrow0) * DFEAT + k + wc0 * 8);
            if (bsec) {
                wh1 = *(const uint4*)(g_WhiT + (size_t)(nBase + wrow1) * DFEAT + k + wc0 * 8);
                wl1 = *(const uint4*)(g_WloT + (size_t)(nBase + wrow1) * DFEAT + k + wc0 * 8);
            }
        }

        #pragma unroll
        for (int kk = 0; kk < BKT; kk += 16) {
            uint32_t ahi[2][4], alo[2][4];
            #pragma unroll
            for (int am = 0; am < 2; am++) {
                const int r = warpM * 32 + am * 16 + lq;
                ahi[am][0] = *(const uint32_t*)&sAhi[r    ][kk + lr * 2    ];
                ahi[am][1] = *(const uint32_t*)&sAhi[r + 8][kk + lr * 2    ];
                ahi[am][2] = *(const uint32_t*)&sAhi[r    ][kk + lr * 2 + 8];
                ahi[am][3] = *(const uint32_t*)&sAhi[r + 8][kk + lr * 2 + 8];
                alo[am][0] = *(const uint32_t*)&sAlo[r    ][kk + lr * 2    ];
                alo[am][1] = *(const uint32_t*)&sAlo[r + 8][kk + lr * 2    ];
                alo[am][2] = *(const uint32_t*)&sAlo[r    ][kk + lr * 2 + 8];
                alo[am][3] = *(const uint32_t*)&sAlo[r + 8][kk + lr * 2 + 8];
            }
            uint32_t bhi[5][2], blo[5][2];
            #pragma unroll
            for (int bn = 0; bn < 5; bn++) {
                const int n = warpN * 40 + bn * 8 + lq;
                bhi[bn][0] = *(const uint32_t*)&sBhi[n][kk + lr * 2    ];
                bhi[bn][1] = *(const uint32_t*)&sBhi[n][kk + lr * 2 + 8];
                blo[bn][0] = *(const uint32_t*)&sBlo[n][kk + lr * 2    ];
                blo[bn][1] = *(const uint32_t*)&sBlo[n][kk + lr * 2 + 8];
            }
            #pragma unroll
            for (int am = 0; am < 2; am++) {
                #pragma unroll
                for (int bn = 0; bn < 5; bn++) {
                    float* c = acc[am][bn];
                    #define MMA(AV, BV)                                               \
                        asm volatile(                                                  \
                            "mma.sync.aligned.m16n8k16.row.col.f32.bf16.bf16.f32 "    \
                            "{%0,%1,%2,%3}, {%4,%5,%6,%7}, {%8,%9}, {%0,%1,%2,%3};"   \
                            : "+f"(c[0]), "+f"(c[1]), "+f"(c[2]), "+f"(c[3])           \
                            : "r"(AV[0]), "r"(AV[1]), "r"(AV[2]), "r"(AV[3]),          \
                              "r"(BV[0]), "r"(BV[1]))
                    MMA(ahi[am], bhi[bn]);
                    MMA(ahi[am], blo[bn]);
                    MMA(alo[am], bhi[bn]);
                    MMA(alo[am], blo[bn]);
                    #undef MMA
                }
            }
        }
        __syncthreads();
    }

    #pragma unroll
    for (int am = 0; am < 2; am++) {
        const int row0 = mBase + warpM * 32 + am * 16 + lq;
        #pragma unroll
        for (int bn = 0; bn < 5; bn++) {
            const int col = nBase + warpN * 40 + bn * 8 + lr * 2;
            *(float2*)&g_partial[zs][row0    ][col] = make_float2(acc[am][bn][0], acc[am][bn][1]);
            *(float2*)&g_partial[zs][row0 + 8][col] = make_float2(acc[am][bn][2], acc[am][bn][3]);
        }
    }
}

// ---------------------------------------------------------------------------
// Kernel 2: per-row S[i] = rowsum(pre_i) - DATTR * logsumexp(pre_i).
// grid 512, block 256: slice reduction split across 160 threads (2x80).
// ---------------------------------------------------------------------------
__global__ __launch_bounds__(256) void rowstats_kernel(const float* __restrict__ bvec)
{
    const int i   = blockIdx.x;
    const int tid = threadIdx.x;

    __shared__ float vhalf[2][DATTR_P];
    __shared__ float vals[DATTR_P];
    __shared__ float sred[8], sse[8], srs[8];

    if (tid < 160) {
        const int half = (tid < 80) ? 0 : 1;
        const int c4   = (tid < 80) ? tid : (tid - 80);
        float4 a = make_float4(0.f, 0.f, 0.f, 0.f);
        #pragma unroll
        for (int s = 0; s < 4; s++) {
            const float4 p = *(const float4*)&g_partial[half * 4 + s][i][c4 * 4];
            a.x += p.x; a.y += p.y; a.z += p.z; a.w += p.w;
        }
        *(float4*)&vhalf[half][c4 * 4] = a;
    }
    __syncthreads();
    if (tid < 80) {
        float4 a = *(const float4*)&vhalf[0][tid * 4];
        const float4 c = *(const float4*)&vhalf[1][tid * 4];
        const float4 bb = (tid < 78) ? *(const float4*)(bvec + tid * 4)
                                     : make_float4(0.f, 0.f, 0.f, 0.f);
        a.x += c.x + bb.x; a.y += c.y + bb.y;
        a.z += c.z + bb.z; a.w += c.w + bb.w;
        *(float4*)&vals[tid * 4] = a;
    }
    __syncthreads();

    float m = -1e30f;
    for (int c = tid; c < DATTR; c += 256) m = fmaxf(m, vals[c]);
    #pragma unroll
    for (int o = 16; o; o >>= 1) m = fmaxf(m, __shfl_xor_sync(0xffffffffu, m, o));
    if ((tid & 31) == 0) sred[tid >> 5] = m;
    __syncthreads();
    m = sred[0];
    #pragma unroll
    for (int w = 1; w < 8; w++) m = fmaxf(m, sred[w]);

    float se = 0.f, rs = 0.f;
    for (int c = tid; c < DATTR; c += 256) {
        const float v = vals[c];
        se += expf(v - m);
        rs += v;
    }
    #pragma unroll
    for (int o = 16; o; o >>= 1) {
        se += __shfl_xor_sync(0xffffffffu, se, o);
        rs += __shfl_xor_sync(0xffffffffu, rs, o);
    }
    if ((tid & 31) == 0) { sse[tid >> 5] = se; srs[tid >> 5] = rs; }
    __syncthreads();

    if (tid == 0) {
        float seT = 0.f, rsT = 0.f;
        #pragma unroll
        for (int w = 0; w < 8; w++) { seT += sse[w]; rsT += srs[w]; }
        g_Sf[i] = rsT - (float)DATTR * (m + logf(seT));
    }
}

// ---------------------------------------------------------------------------
// Kernel 3: pair loss via per-row coefficients + SIMD byte-packed label scan.
//   sum_{i<j,same}(S_j - S_i) = sum_t coef_t * S_t,
//   coef_t = 2*cnt_lt + 1 - cnt_all;  pairs = sum_t cnt_lt.
// NUMERICS: within each label group sum(coef)=0, so we may shift S by any
// constant. Use S - S[0] (terms drop 1e4 -> ~1e2) and accumulate the dot
// product in double (512 DADDs, negligible) to kill fp32 cancellation.
// ---------------------------------------------------------------------------
__global__ __launch_bounds__(512) void pair_loss_kernel(
    const int* __restrict__ labw, float* __restrict__ out)
{
    __shared__ int           slab[B_SZ];
    __shared__ unsigned int  pw[B_SZ / 4];
    __shared__ int           s_not64;
    __shared__ double        swsum[16];
    __shared__ unsigned int  swcnt[16];

    const int t = threadIdx.x;
    if (t == 0) s_not64 = 0;
    __syncthreads();

    // label dtype sniff: int64 buffers have zero odd words (labels < 150)
    if (t < 256 && labw[2 * t + 1] != 0) atomicOr(&s_not64, 1);
    __syncthreads();

    const bool is64 = (s_not64 == 0);
    slab[t] = is64 ? labw[2 * t] : labw[t];
    __syncthreads();

    if (t < B_SZ / 4) {
        pw[t] = (unsigned)(slab[4 * t] & 0xFF)
              | ((unsigned)(slab[4 * t + 1] & 0xFF) << 8)
              | ((unsigned)(slab[4 * t + 2] & 0xFF) << 16)
              | ((unsigned)(slab[4 * t + 3] & 0xFF) << 24);
    }
    __syncthreads();

    const unsigned ml4   = (unsigned)(slab[t] & 0xFF) * 0x01010101u;
    const int      wt    = t >> 2;
    const unsigned bmask = (1u << (8 * (t & 3))) - 1u;   // bytes strictly below me

    int cnt_lt = 0, cnt_all = 0;
    #pragma unroll 8
    for (int w = 0; w < B_SZ / 4; w++) {
        const unsigned m = __vcmpeq4(pw[w], ml4);
        const int c = __popc(m) >> 3;
        cnt_all += c;
        if (w < wt)       cnt_lt += c;
        else if (w == wt) cnt_lt += __popc(m & bmask) >> 3;
    }

    const float  ref   = g_Sf[0];
    double       local = (double)(2 * cnt_lt + 1 - cnt_all) *
                         (double)(g_Sf[t] - ref);
    unsigned int cnt   = (unsigned int)cnt_lt;

    #pragma unroll
    for (int o = 16; o; o >>= 1) {
        local += __shfl_xor_sync(0xffffffffu, local, o);
        cnt   += __shfl_xor_sync(0xffffffffu, cnt, o);
    }
    if ((t & 31) == 0) { swsum[t >> 5] = local; swcnt[t >> 5] = cnt; }
    __syncthreads();

    if (t == 0) {
        double s = 0.0; unsigned int c = 0;
        #pragma unroll
        for (int w = 0; w < 16; w++) { s += swsum[w]; c += swcnt[w]; }
        out[0] = (float)((c > 0) ? (s / (double)c) : s);
    }
}

// ---------------------------------------------------------------------------
extern "C" void kernel_launch(void* const* d_in, const int* in_sizes, int n_in,
                              void* d_out, int out_size)
{
    const float* x   = (const float*)d_in[0];      // [512, 2048]
    const float* Wm  = (const float*)d_in[1];      // [2048, 312]
    const float* b   = (const float*)d_in[2];      // [312]
    // d_in[3] = seen_att : unused (cancels exactly for same-label pairs)
    const int*   lab = (const int*)d_in[4];        // [512] labels

    split_w_kernel<<<dim3(10, 32), 256>>>(Wm);
    mma_gemm_kernel<<<dim3(DATTR_P / NT_BLK, B_SZ / MT_BLK, KSPLIT), 256>>>(x);
    rowstats_kernel<<<B_SZ, 256>>>(b);
    pair_loss_kernel<<<1, B_SZ>>>(lab, (float*)d_out);
}

// round 11
// speedup vs baseline: 2.5504x; 1.2439x over previous
#include <cuda_runtime.h>
#include <cuda_bf16.h>
#include <math.h>
#include <stdint.h>

// Problem constants
#define B_SZ    512
#define DFEAT   2048
#define DATTR   312
#define DATTR_P 320              // N padded to 4*80
#define NCLS_P  152              // class table stride

// GEMM tiling: D[512,320] = X[512,2048] @ W^T, bf16 hi/lo x4-term split
#define MT_BLK  128              // M per CTA
#define NT_BLK  80               // N per CTA -> 4 n-tiles, grid 128 = one wave
#define BKT     32               // K per smem tile
#define KSPLIT  8
#define KSLICE  (DFEAT / KSPLIT) // 256

// Scratch (__device__ globals: allocation-free, zero-initialized at load)
__device__ __nv_bfloat16 g_WhiT[DATTR_P * DFEAT];   // W^T K-major; rows >=312 stay 0
__device__ __nv_bfloat16 g_WloT[DATTR_P * DFEAT];
__device__ float g_partial[KSPLIT][B_SZ][DATTR_P];
__device__ float g_Sf[B_SZ];

// ---------------------------------------------------------------------------
// Kernel 0: W [2048,312] -> W^T [320,2048] bf16 hi/lo, vectorized.
// grid (10 n-tiles of 32, 32 k-tiles of 64) = 320 blocks, 256 threads.
// ---------------------------------------------------------------------------
__global__ __launch_bounds__(256) void split_w_kernel(const float* __restrict__ Wm)
{
    __shared__ float t[64][33];
    const int n0 = blockIdx.x * 32, k0 = blockIdx.y * 64;
    const int tid = threadIdx.x;

    {
        const int r = tid >> 2, q = tid & 3;
        #pragma unroll
        for (int h = 0; h < 2; h++) {
            const int qq = q + 4 * h;
            const int n = n0 + qq * 4;
            const float4 v = (n < DATTR)
                ? *(const float4*)(Wm + (size_t)(k0 + r) * DATTR + n)
                : make_float4(0.f, 0.f, 0.f, 0.f);
            t[r][qq * 4 + 0] = v.x;
            t[r][qq * 4 + 1] = v.y;
            t[r][qq * 4 + 2] = v.z;
            t[r][qq * 4 + 3] = v.w;
        }
    }
    __syncthreads();

    {
        const int nl = tid >> 3, kc = tid & 7;
        const int n = n0 + nl;
        if (n < DATTR) {
            __nv_bfloat16 hi[8], lo[8];
            #pragma unroll
            for (int j = 0; j < 8; j++) {
                const float v = t[kc * 8 + j][nl];
                hi[j] = __float2bfloat16_rn(v);
                lo[j] = __float2bfloat16_rn(v - __bfloat162float(hi[j]));
            }
            const size_t off = (size_t)n * DFEAT + k0 + kc * 8;
            *(uint4*)(g_WhiT + off) = *(const uint4*)hi;
            *(uint4*)(g_WloT + off) = *(const uint4*)lo;
        }
    }
}

// ---------------------------------------------------------------------------
// Kernel 1: fused bf16 mma.sync GEMM with inline X hi/lo split.
// grid (4 n-tiles, 4 m-tiles, 8 k-slices) = 128 CTAs (one wave), 256 threads.
// ---------------------------------------------------------------------------
__global__ __launch_bounds__(256) void mma_gemm_kernel(const float* __restrict__ X)
{
    __shared__ __nv_bfloat16 sAhi[MT_BLK][40];
    __shared__ __nv_bfloat16 sAlo[MT_BLK][40];
    __shared__ __nv_bfloat16 sBhi[NT_BLK][40];
    __shared__ __nv_bfloat16 sBlo[NT_BLK][40];

    const int tid   = threadIdx.x;
    const int wid   = tid >> 5;
    const int lane  = tid & 31;
    const int warpM = wid >> 1;          // 0..3
    const int warpN = wid & 1;           // 0..1
    const int nt = blockIdx.x, mt = blockIdx.y, zs = blockIdx.z;

    const int mBase = mt * MT_BLK;
    const int nBase = nt * NT_BLK;
    const int k0    = zs * KSLICE;

    const int lq = lane >> 2;
    const int lr = lane & 3;

    float4 xa[4];
    uint4  wh0, wl0, wh1, wl1;
    const int arow  = tid >> 3, ac = tid & 7;
    const int wrow0 = tid >> 2, wc0 = tid & 3;
    const int wrow1 = 64 + (tid >> 2);
    const bool bsec = (tid < 64);

    float acc[2][5][4] = {};

    {
        const int k = k0;
        #pragma unroll
        for (int it = 0; it < 4; it++)
            xa[it] = *(const float4*)(X + (size_t)(mBase + arow + 32 * it) * DFEAT + k + ac * 4);
        wh0 = *(const uint4*)(g_WhiT + (size_t)(nBase + wrow0) * DFEAT + k + wc0 * 8);
        wl0 = *(const uint4*)(g_WloT + (size_t)(nBase + wrow0) * DFEAT + k + wc0 * 8);
        if (bsec) {
            wh1 = *(const uint4*)(g_WhiT + (size_t)(nBase + wrow1) * DFEAT + k + wc0 * 8);
            wl1 = *(const uint4*)(g_WloT + (size_t)(nBase + wrow1) * DFEAT + k + wc0 * 8);
        }
    }

    for (int kt = 0; kt < KSLICE; kt += BKT) {
        #pragma unroll
        for (int it = 0; it < 4; it++) {
            const float4 v = xa[it];
            const int row = arow + 32 * it;
            const __nv_bfloat16 h0 = __float2bfloat16_rn(v.x), h1 = __float2bfloat16_rn(v.y);
            const __nv_bfloat16 h2 = __float2bfloat16_rn(v.z), h3 = __float2bfloat16_rn(v.w);
            *(__nv_bfloat162*)&sAhi[row][ac * 4]     = __nv_bfloat162(h0, h1);
            *(__nv_bfloat162*)&sAhi[row][ac * 4 + 2] = __nv_bfloat162(h2, h3);
            *(__nv_bfloat162*)&sAlo[row][ac * 4] = __nv_bfloat162(
                __float2bfloat16_rn(v.x - __bfloat162float(h0)),
                __float2bfloat16_rn(v.y - __bfloat162float(h1)));
            *(__nv_bfloat162*)&sAlo[row][ac * 4 + 2] = __nv_bfloat162(
                __float2bfloat16_rn(v.z - __bfloat162float(h2)),
                __float2bfloat16_rn(v.w - __bfloat162float(h3)));
        }
        *(uint4*)&sBhi[wrow0][wc0 * 8] = wh0;
        *(uint4*)&sBlo[wrow0][wc0 * 8] = wl0;
        if (bsec) {
            *(uint4*)&sBhi[wrow1][wc0 * 8] = wh1;
            *(uint4*)&sBlo[wrow1][wc0 * 8] = wl1;
        }
        __syncthreads();

        if (kt + BKT < KSLICE) {
            const int k = k0 + kt + BKT;
            #pragma unroll
            for (int it = 0; it < 4; it++)
                xa[it] = *(const float4*)(X + (size_t)(mBase + arow + 32 * it) * DFEAT + k + ac * 4);
            wh0 = *(const uint4*)(g_WhiT + (size_t)(nBase + wrow0) * DFEAT + k + wc0 * 8);
            wl0 = *(const uint4*)(g_WloT + (size_t)(nBase + wrow0) * DFEAT + k + wc0 * 8);
            if (bsec) {
                wh1 = *(const uint4*)(g_WhiT + (size_t)(nBase + wrow1) * DFEAT + k + wc0 * 8);
                wl1 = *(const uint4*)(g_WloT + (size_t)(nBase + wrow1) * DFEAT + k + wc0 * 8);
            }
        }

        #pragma unroll
        for (int kk = 0; kk < BKT; kk += 16) {
            uint32_t ahi[2][4], alo[2][4];
            #pragma unroll
            for (int am = 0; am < 2; am++) {
                const int r = warpM * 32 + am * 16 + lq;
                ahi[am][0] = *(const uint32_t*)&sAhi[r    ][kk + lr * 2    ];
                ahi[am][1] = *(const uint32_t*)&sAhi[r + 8][kk + lr * 2    ];
                ahi[am][2] = *(const uint32_t*)&sAhi[r    ][kk + lr * 2 + 8];
                ahi[am][3] = *(const uint32_t*)&sAhi[r + 8][kk + lr * 2 + 8];
                alo[am][0] = *(const uint32_t*)&sAlo[r    ][kk + lr * 2    ];
                alo[am][1] = *(const uint32_t*)&sAlo[r + 8][kk + lr * 2    ];
                alo[am][2] = *(const uint32_t*)&sAlo[r    ][kk + lr * 2 + 8];
                alo[am][3] = *(const uint32_t*)&sAlo[r + 8][kk + lr * 2 + 8];
            }
            uint32_t bhi[5][2], blo[5][2];
            #pragma unroll
            for (int bn = 0; bn < 5; bn++) {
                const int n = warpN * 40 + bn * 8 + lq;
                bhi[bn][0] = *(const uint32_t*)&sBhi[n][kk + lr * 2    ];
                bhi[bn][1] = *(const uint32_t*)&sBhi[n][kk + lr * 2 + 8];
                blo[bn][0] = *(const uint32_t*)&sBlo[n][kk + lr * 2    ];
                blo[bn][1] = *(const uint32_t*)&sBlo[n][kk + lr * 2 + 8];
            }
            #pragma unroll
            for (int am = 0; am < 2; am++) {
                #pragma unroll
                for (int bn = 0; bn < 5; bn++) {
                    float* c = acc[am][bn];
                    #define MMA(AV, BV)                                               \
                        asm volatile(                                                  \
                            "mma.sync.aligned.m16n8k16.row.col.f32.bf16.bf16.f32 "    \
                            "{%0,%1,%2,%3}, {%4,%5,%6,%7}, {%8,%9}, {%0,%1,%2,%3};"   \
                            : "+f"(c[0]), "+f"(c[1]), "+f"(c[2]), "+f"(c[3])           \
                            : "r"(AV[0]), "r"(AV[1]), "r"(AV[2]), "r"(AV[3]),          \
                              "r"(BV[0]), "r"(BV[1]))
                    MMA(ahi[am], bhi[bn]);
                    MMA(ahi[am], blo[bn]);
                    MMA(alo[am], bhi[bn]);
                    MMA(alo[am], blo[bn]);
                    #undef MMA
                }
            }
        }
        __syncthreads();
    }

    #pragma unroll
    for (int am = 0; am < 2; am++) {
        const int row0 = mBase + warpM * 32 + am * 16 + lq;
        #pragma unroll
        for (int bn = 0; bn < 5; bn++) {
            const int col = nBase + warpN * 40 + bn * 8 + lr * 2;
            *(float2*)&g_partial[zs][row0    ][col] = make_float2(acc[am][bn][0], acc[am][bn][1]);
            *(float2*)&g_partial[zs][row0 + 8][col] = make_float2(acc[am][bn][2], acc[am][bn][3]);
        }
    }
}

// ---------------------------------------------------------------------------
// Kernel 2: per-row S[i] = rowsum(pre_i) - DATTR * logsumexp(pre_i).
// grid 512, block 256.
// ---------------------------------------------------------------------------
__global__ __launch_bounds__(256) void rowstats_kernel(const float* __restrict__ bvec)
{
    const int i   = blockIdx.x;
    const int tid = threadIdx.x;

    __shared__ float vhalf[2][DATTR_P];
    __shared__ float vals[DATTR_P];
    __shared__ float sred[8], sse[8], srs[8];

    if (tid < 160) {
        const int half = (tid < 80) ? 0 : 1;
        const int c4   = (tid < 80) ? tid : (tid - 80);
        float4 a = make_float4(0.f, 0.f, 0.f, 0.f);
        #pragma unroll
        for (int s = 0; s < 4; s++) {
            const float4 p = *(const float4*)&g_partial[half * 4 + s][i][c4 * 4];
            a.x += p.x; a.y += p.y; a.z += p.z; a.w += p.w;
        }
        *(float4*)&vhalf[half][c4 * 4] = a;
    }
    __syncthreads();
    if (tid < 80) {
        float4 a = *(const float4*)&vhalf[0][tid * 4];
        const float4 c = *(const float4*)&vhalf[1][tid * 4];
        const float4 bb = (tid < 78) ? *(const float4*)(bvec + tid * 4)
                                     : make_float4(0.f, 0.f, 0.f, 0.f);
        a.x += c.x + bb.x; a.y += c.y + bb.y;
        a.z += c.z + bb.z; a.w += c.w + bb.w;
        *(float4*)&vals[tid * 4] = a;
    }
    __syncthreads();

    float m = -1e30f;
    for (int c = tid; c < DATTR; c += 256) m = fmaxf(m, vals[c]);
    #pragma unroll
    for (int o = 16; o; o >>= 1) m = fmaxf(m, __shfl_xor_sync(0xffffffffu, m, o));
    if ((tid & 31) == 0) sred[tid >> 5] = m;
    __syncthreads();
    m = sred[0];
    #pragma unroll
    for (int w = 1; w < 8; w++) m = fmaxf(m, sred[w]);

    float se = 0.f, rs = 0.f;
    for (int c = tid; c < DATTR; c += 256) {
        const float v = vals[c];
        se += expf(v - m);
        rs += v;
    }
    #pragma unroll
    for (int o = 16; o; o >>= 1) {
        se += __shfl_xor_sync(0xffffffffu, se, o);
        rs += __shfl_xor_sync(0xffffffffu, rs, o);
    }
    if ((tid & 31) == 0) { sse[tid >> 5] = se; srs[tid >> 5] = rs; }
    __syncthreads();

    if (tid == 0) {
        float seT = 0.f, rsT = 0.f;
        #pragma unroll
        for (int w = 0; w < 8; w++) { seT += sse[w]; rsT += srs[w]; }
        g_Sf[i] = rsT - (float)DATTR * (m + logf(seT));
    }
}

// ---------------------------------------------------------------------------
// Kernel 3: pair loss, O(B) per thread.
//   loss_sum = sum_t coef_t * (S_t - S_0),  coef_t = 2*rank_t + 1 - cnt_all_t
//   pairs    = sum_t rank_t
// rank_t (count of earlier same-label rows) = per-warp class-count table for
// earlier warps + __match_any_sync within my warp. ~16 LDS + 20 ALU / thread.
// Double accumulation of the (shifted) dot kills fp32 cancellation.
// ---------------------------------------------------------------------------
__global__ __launch_bounds__(512) void pair_loss_kernel(
    const int* __restrict__ labw, float* __restrict__ out)
{
    __shared__ int           slab[B_SZ];
    __shared__ int           table[16][NCLS_P];   // per-warp class counts
    __shared__ int           s_not64;
    __shared__ double        swsum[16];
    __shared__ unsigned int  swcnt[16];

    const int t    = threadIdx.x;
    const int wrp  = t >> 5;
    const int lane = t & 31;

    if (t == 0) s_not64 = 0;
    #pragma unroll
    for (int j = 0; j < (16 * NCLS_P + 511) / 512; j++) {
        const int idx = t + 512 * j;
        if (idx < 16 * NCLS_P) ((int*)table)[idx] = 0;
    }
    __syncthreads();

    // label dtype sniff: int64 buffers have zero odd words (labels < 150)
    if (t < 256 && labw[2 * t + 1] != 0) atomicOr(&s_not64, 1);
    __syncthreads();

    const bool is64 = (s_not64 == 0);
    const int  li   = is64 ? labw[2 * t] : labw[t];
    slab[t] = li;
    atomicAdd(&table[wrp][li], 1);
    __syncthreads();

    // rank within my class
    const unsigned mmask = __match_any_sync(0xffffffffu, li);
    int rank = __popc(mmask & ((1u << lane) - 1u));
    int cnt_all = 0;
    #pragma unroll
    for (int w = 0; w < 16; w++) {
        const int c = table[w][li];
        cnt_all += c;
        if (w < wrp) rank += c;
    }

    const float  ref   = g_Sf[0];
    double       local = (double)(2 * rank + 1 - cnt_all) *
                         (double)(g_Sf[t] - ref);
    unsigned int cnt   = (unsigned int)rank;

    #pragma unroll
    for (int o = 16; o; o >>= 1) {
        local += __shfl_xor_sync(0xffffffffu, local, o);
        cnt   += __shfl_xor_sync(0xffffffffu, cnt, o);
    }
    if (lane == 0) { swsum[wrp] = local; swcnt[wrp] = cnt; }
    __syncthreads();

    if (t == 0) {
        double s = 0.0; unsigned int c = 0;
        #pragma unroll
        for (int w = 0; w < 16; w++) { s += swsum[w]; c += swcnt[w]; }
        out[0] = (float)((c > 0) ? (s / (double)c) : s);
    }
}

// ---------------------------------------------------------------------------
extern "C" void kernel_launch(void* const* d_in, const int* in_sizes, int n_in,
                              void* d_out, int out_size)
{
    const float* x   = (const float*)d_in[0];      // [512, 2048]
    const float* Wm  = (const float*)d_in[1];      // [2048, 312]
    const float* b   = (const float*)d_in[2];      // [312]
    // d_in[3] = seen_att : unused (cancels exactly for same-label pairs)
    const int*   lab = (const int*)d_in[4];        // [512] labels

    split_w_kernel<<<dim3(10, 32), 256>>>(Wm);
    mma_gemm_kernel<<<dim3(DATTR_P / NT_BLK, B_SZ / MT_BLK, KSPLIT), 256>>>(x);
    rowstats_kernel<<<B_SZ, 256>>>(b);
    pair_loss_kernel<<<1, B_SZ>>>(lab, (float*)d_out);
}